// round 5
// baseline (speedup 1.0000x reference)
#include <cuda_runtime.h>
#include <cstdint>

#define BATCH     512
#define SIZE_IN   1024
#define SIZE_OUT  256
#define NQ        16

#define BT        64                 // batch tile per CTA
#define ISPLIT    37                 // 8 * 37 = 296 = 148 SMs * 2 CTAs exactly
#define ICHUNKMAX 28                 // ceil(1024/37)
#define NTHREADS  512

// out[b,o] = bias[o]  (atomic accumulation target)
__global__ void il_init_out(const float* __restrict__ bias, float* __restrict__ out) {
    int i = blockIdx.x * blockDim.x + threadIdx.x;
    if (i < BATCH * SIZE_OUT) out[i] = bias[i & (SIZE_OUT - 1)];
}

__device__ __forceinline__ void mbar_init(uint32_t mb, uint32_t count) {
    asm volatile("mbarrier.init.shared.b64 [%0], %1;" :: "r"(mb), "r"(count) : "memory");
}
__device__ __forceinline__ void mbar_wait(uint32_t mb, uint32_t parity) {
    asm volatile(
        "{\n\t.reg .pred P;\n"
        "WL%=:\n\t"
        "mbarrier.try_wait.parity.acquire.cta.shared::cta.b64 P, [%0], %1, 0x989680;\n\t"
        "@!P bra WL%=;\n\t}"
        :: "r"(mb), "r"(parity) : "memory");
}

// Stage the 16 candidate 1 KB rows of feature i into smem via bulk-async copy.
// Single elected thread; 16 KB total signalled through the mbarrier.
__device__ __forceinline__ void stage_feature(uint32_t sdst, const float* __restrict__ table,
                                              int i, uint32_t mb) {
    asm volatile("mbarrier.arrive.expect_tx.shared::cta.b64 _, [%0], %1;"
                 :: "r"(mb), "r"(16384u) : "memory");
    #pragma unroll
    for (int q = 0; q < NQ; q++) {
        const void* src = table + ((size_t)q * SIZE_IN + i) * SIZE_OUT;
        asm volatile(
            "cp.async.bulk.shared::cta.global.mbarrier::complete_tx::bytes [%0], [%1], %2, [%3];"
            :: "r"(sdst + (uint32_t)q * 1024u), "l"(src), "r"(1024u), "r"(mb) : "memory");
    }
}

// One CTA: 64 batches x (27..28) features x 256 outputs.
// Double-buffered 16 KB weight stage filled by cp.async.bulk one feature ahead.
__global__ __launch_bounds__(NTHREADS, 2)
void il_main(const float* __restrict__ x,
             const int* __restrict__ indices,   // JAX canonicalizes int64 -> int32
             const float* __restrict__ table,
             float* __restrict__ out) {
    const int b0  = blockIdx.x * BT;
    const int lo  = (int)(((long long)blockIdx.y * SIZE_IN) / ISPLIT);
    const int hi  = (int)(((long long)(blockIdx.y + 1) * SIZE_IN) / ISPLIT);
    const int len = hi - lo;             // 27 or 28
    const int t   = threadIdx.x;
    const int og  = t & 63;              // output columns og*4 .. og*4+3
    const int bg  = t >> 6;              // batches bg*8 .. bg*8+7

    __shared__ __align__(1024) float sW[2][NQ * SIZE_OUT];   // 2 x 16 KB
    __shared__ float2 sxq[BT][ICHUNKMAX];                     // {x, float-bits of q*256}
    __shared__ __align__(8) unsigned long long mbar_store[2];

    const uint32_t sW0 = (uint32_t)__cvta_generic_to_shared(&sW[0][0]);
    const uint32_t mb0 = (uint32_t)__cvta_generic_to_shared(&mbar_store[0]);
    const uint32_t mb1 = (uint32_t)__cvta_generic_to_shared(&mbar_store[1]);

    if (t == 0) {
        mbar_init(mb0, 1);
        mbar_init(mb1, 1);
        asm volatile("fence.proxy.async.shared::cta;" ::: "memory");
    }

    // Preload x and quantile offsets for the (64 batch x len) tile.
    // 8 threads per batch row, each covers features lane8 + 8k (k<4), guarded.
    {
        const int bl    = t >> 3;        // 0..63
        const int lane8 = t & 7;
        const float* xp = x       + (size_t)(b0 + bl) * SIZE_IN + lo;
        const int*   qp = indices + (size_t)(b0 + bl) * SIZE_IN + lo;
        #pragma unroll
        for (int k = 0; k < 4; k++) {
            const int ii = lane8 + k * 8;
            if (ii < len) {
                sxq[bl][ii] = make_float2(xp[ii], __int_as_float(qp[ii] * SIZE_OUT));
            }
        }
    }

    __syncthreads();   // mbar init + sxq visible; required before first bulk issue

    if (t == 0) stage_feature(sW0, table, lo, mb0);

    float4 acc[8];
    #pragma unroll
    for (int k = 0; k < 8; k++) acc[k] = make_float4(0.f, 0.f, 0.f, 0.f);

    for (int ii = 0; ii < len; ii++) {
        const int buf = ii & 1;

        if (ii) __syncthreads();   // everyone finished reading buf^1 (iteration ii-1)

        // Prefetch feature ii+1 into the other buffer.
        if (t == 0 && ii + 1 < len) {
            stage_feature(sW0 + (uint32_t)((buf ^ 1) * NQ * SIZE_OUT) * 4u,
                          table, lo + ii + 1, (buf ^ 1) ? mb1 : mb0);
        }

        mbar_wait(buf ? mb1 : mb0, (ii >> 1) & 1);

        const float* wbuf = sW[buf];
        #pragma unroll
        for (int bl = 0; bl < 8; bl++) {
            const int b = bg * 8 + bl;                    // uniform per warp -> LDS broadcast
            const float2 v = sxq[b][ii];                  // {x, q*256 offset}
            const int off = __float_as_int(v.y);
            const float4 w = *reinterpret_cast<const float4*>(wbuf + off + og * 4);
            acc[bl].x += v.x * w.x;
            acc[bl].y += v.x * w.y;
            acc[bl].z += v.x * w.z;
            acc[bl].w += v.x * w.w;
        }
    }

    // Combine split-k partials.
    #pragma unroll
    for (int bl = 0; bl < 8; bl++) {
        const int b = b0 + bg * 8 + bl;
        float* op = out + (size_t)b * SIZE_OUT + og * 4;
        atomicAdd(op + 0, acc[bl].x);
        atomicAdd(op + 1, acc[bl].y);
        atomicAdd(op + 2, acc[bl].z);
        atomicAdd(op + 3, acc[bl].w);
    }
}

extern "C" void kernel_launch(void* const* d_in, const int* in_sizes, int n_in,
                              void* d_out, int out_size) {
    const float* x       = (const float*)d_in[0];
    const int*   indices = (const int*)d_in[1];
    const float* table   = (const float*)d_in[2];
    const float* bias    = (const float*)d_in[3];
    float*       out     = (float*)d_out;

    il_init_out<<<(BATCH * SIZE_OUT + 255) / 256, 256>>>(bias, out);

    dim3 grid(BATCH / BT, ISPLIT);   // 8 x 37 = 296 CTAs = 148 SMs * 2
    il_main<<<grid, NTHREADS>>>(x, indices, table, out);
}